// round 17
// baseline (speedup 1.0000x reference)
#include <cuda_runtime.h>
#include <math.h>

#define BB   1024
#define TT   512
#define HH   64
#define ROWS 8
#define NTHR 256
#define FTHR 512           // fused kernel threads
#define IPITCH 68          // words per row in h buffers (conflict-free padding)
#define HBUF  (8 * IPITCH) // 544 words per h buffer
#define PPITCH 260         // partial-sum row pitch
#define PBUF  (8 * PPITCH) // 2080 words per partial buffer
#define TCH  16            // t-chunks for pre-GEMM
#define TPC  (TT / TCH)    // 32 timesteps per pre-GEMM CTA
#define LOG2E 1.4426950408889634f

// Scratch (static __device__ arrays are the allowed scratch mechanism)
__device__ float g_pre[(size_t)BB * TT * 256];   // layer-0 x-projection [cta][t][g][r]
__device__ float g_hlast[BB * HH];               // layer-1 final hidden state

__device__ __forceinline__ void fma2(unsigned long long &d,
                                     unsigned long long a, unsigned long long b) {
    asm("fma.rn.f32x2 %0, %1, %2, %0;" : "+l"(d) : "l"(a), "l"(b));
}
__device__ __forceinline__ float2 unpack2(unsigned long long v) {
    float2 f; asm("mov.b64 {%0, %1}, %2;" : "=f"(f.x), "=f"(f.y) : "l"(v)); return f;
}
__device__ __forceinline__ float ex2f(float x) {
    float r; asm("ex2.approx.f32 %0, %1;" : "=f"(r) : "f"(x)); return r;
}
__device__ __forceinline__ float rcpf(float x) {
    float r; asm("rcp.approx.f32 %0, %1;" : "=f"(r) : "f"(x)); return r;
}
__device__ __forceinline__ float sum2(unsigned long long v) {
    float2 f = unpack2(v); return f.x + f.y;
}

// ---- paired activations: 2 values share ONE rcp (overflow-safe |x| form) ----
// sigmoid pair: e = 2^(-1.4427|z|) in (0,1]; sig = num / (1+e), num = (z>=0)?1:e
__device__ __forceinline__ void sig2(float z0, float z1, float &s0, float &s1) {
    float e0 = ex2f(-LOG2E * fabsf(z0));
    float e1 = ex2f(-LOG2E * fabsf(z1));
    float n0 = (z0 >= 0.0f) ? 1.0f : e0;
    float n1 = (z1 >= 0.0f) ? 1.0f : e1;
    float d0 = 1.0f + e0, d1 = 1.0f + e1;
    float rp = rcpf(d0 * d1);           // d0*d1 in (1,4] -> always safe
    s0 = n0 * d1 * rp;
    s1 = n1 * d0 * rp;
}
// tanh pair: e = 2^(-2.8854|z|) in (0,1]; tanh = sign(z)*(1-e)/(1+e)
__device__ __forceinline__ void tanh2(float z0, float z1, float &t0, float &t1) {
    float e0 = ex2f(-2.0f * LOG2E * fabsf(z0));
    float e1 = ex2f(-2.0f * LOG2E * fabsf(z1));
    float d0 = 1.0f + e0, d1 = 1.0f + e1;
    float rp = rcpf(d0 * d1);
    t0 = copysignf((1.0f - e0) * d1 * rp, z0);
    t1 = copysignf((1.0f - e1) * d0 * rp, z1);
}

// ---------------------------------------------------------------------------
// pre0[b][t][g] = b_ih0[g]+b_hh0[g] + x[b][t] @ w_ih0[g]   (time-parallel)
// R14/R15 tiling (4 timesteps/iter) + register prefetch of the next x tile:
// LDG(i+1) issues under compute(i), STS happens from registers between the
// two barriers (no exposed LDG->STS chain).
// ---------------------------------------------------------------------------
__global__ void __launch_bounds__(NTHR, 2)
gemm_pre(const float* __restrict__ x_in,
         const float* __restrict__ w_ih,
         const float* __restrict__ b_ih, const float* __restrict__ b_hh)
{
    extern __shared__ float sm[];
    float* wq = sm;                  // [16 kk][256 g][4 kp] = 16384 floats (64 KB)
    float* xb = sm + 16384;          // [4 tb][8 rows][IPITCH]

    const int tid = threadIdx.x;
    const int j   = tid >> 2;
    const int rg  = tid & 3;
    const int r0  = rg * 2;
    const int row_base = blockIdx.x * ROWS;
    const int t0 = blockIdx.y * TPC;

    for (int idx = tid; idx < 64 * 256; idx += NTHR) {
        int kp = idx & 3;
        int g  = (idx >> 2) & 255;
        int kk = idx >> 10;
        wq[idx] = w_ih[g * 64 + kk * 4 + kp];
    }

    float bias[4];
    #pragma unroll
    for (int q = 0; q < 4; q++) bias[q] = b_ih[q * 64 + j] + b_hh[q * 64 + j];

    float* outp = g_pre + (size_t)blockIdx.x * TT * 2048;

    // per-thread x-load mapping (8 elements per 4-t tile)
    int ltb[8], lr[8], lu[8];
    #pragma unroll
    for (int e = 0; e < 8; e++) {
        int ii = tid + e * 256;
        ltb[e] = ii >> 9;
        lr[e]  = (ii & 511) >> 6;
        lu[e]  = ii & 63;
    }

    // prefetch tile 0
    float xr[8];
    #pragma unroll
    for (int e = 0; e < 8; e++)
        xr[e] = x_in[((size_t)(row_base + lr[e]) * TT + (t0 + ltb[e])) * HH + lu[e]];

    for (int it = 0; it < TPC / 4; it++) {
        const int t = t0 + it * 4;
        __syncthreads();   // previous compute finished reading xb
        #pragma unroll
        for (int e = 0; e < 8; e++)
            xb[(ltb[e] * 8 + lr[e]) * IPITCH + lu[e]] = xr[e];
        __syncthreads();

        // prefetch next tile (latency hidden under compute below)
        if (it + 1 < TPC / 4) {
            const int tn = t + 4;
            #pragma unroll
            for (int e = 0; e < 8; e++)
                xr[e] = x_in[((size_t)(row_base + lr[e]) * TT + (tn + ltb[e])) * HH + lu[e]];
        }

        unsigned long long acc[4][2][4];   // [tb][row][q]
        #pragma unroll
        for (int tb = 0; tb < 4; tb++)
            #pragma unroll
            for (int r = 0; r < 2; r++)
                #pragma unroll
                for (int q = 0; q < 4; q++) acc[tb][r][q] = 0ull;

        const float* wp = wq + j * 4;

        #pragma unroll
        for (int kk = 0; kk < 16; kk++) {
            const float* wc = wp + kk * 1024;
            ulonglong2 w2[4];
            #pragma unroll
            for (int q = 0; q < 4; q++)
                w2[q] = *reinterpret_cast<const ulonglong2*>(wc + q * 256);

            #pragma unroll
            for (int tb = 0; tb < 2; tb++) {
                const float* va = xb + (tb * 8 + r0) * IPITCH + kk * 4;
                ulonglong2 v0 = *reinterpret_cast<const ulonglong2*>(va);
                ulonglong2 v1 = *reinterpret_cast<const ulonglong2*>(va + IPITCH);
                #pragma unroll
                for (int q = 0; q < 4; q++) {
                    fma2(acc[tb][0][q], v0.x, w2[q].x);
                    fma2(acc[tb][0][q], v0.y, w2[q].y);
                    fma2(acc[tb][1][q], v1.x, w2[q].x);
                    fma2(acc[tb][1][q], v1.y, w2[q].y);
                }
            }
            #pragma unroll
            for (int tb = 2; tb < 4; tb++) {
                const float* va = xb + (tb * 8 + r0) * IPITCH + kk * 4;
                ulonglong2 v0 = *reinterpret_cast<const ulonglong2*>(va);
                ulonglong2 v1 = *reinterpret_cast<const ulonglong2*>(va + IPITCH);
                #pragma unroll
                for (int q = 0; q < 4; q++) {
                    fma2(acc[tb][0][q], v0.x, w2[q].x);
                    fma2(acc[tb][0][q], v0.y, w2[q].y);
                    fma2(acc[tb][1][q], v1.x, w2[q].x);
                    fma2(acc[tb][1][q], v1.y, w2[q].y);
                }
            }
        }

        #pragma unroll
        for (int tb = 0; tb < 4; tb++) {
            float* ob = outp + (size_t)(t + tb) * 2048;
            #pragma unroll
            for (int q = 0; q < 4; q++) {
                float2 f0 = unpack2(acc[tb][0][q]);
                float2 f1 = unpack2(acc[tb][1][q]);
                float2 st = make_float2(f0.x + f0.y + bias[q], f1.x + f1.y + bias[q]);
                *reinterpret_cast<float2*>(ob + (q * 64 + j) * 8 + r0) = st;
            }
        }
    }
}

// ---------------------------------------------------------------------------
// Fused 2-layer recurrence, BALANCED software pipeline (512 threads).
// R12/R16 structure + paired-rcp activations + hoisted partA loads.
// ---------------------------------------------------------------------------
__global__ void __launch_bounds__(FTHR, 1)
lstm_fused(const float* __restrict__ w_hh0,
           const float* __restrict__ w_ih1, const float* __restrict__ w_hh1,
           const float* __restrict__ b_ih1, const float* __restrict__ b_hh1)
{
    extern __shared__ float sm[];
    float* wq0  = sm;                 // w_hh0 gate-major, 16384 floats
    float* wq1i = sm + 16384;         // w_ih1 gate-major
    float* wq1h = sm + 32768;         // w_hh1 gate-major
    float* h1b  = sm + 49152;         // [3][8][IPITCH]
    float* h2b  = h1b + 3 * HBUF;     // [2][8][IPITCH]
    float* pAb  = h2b + 2 * HBUF;     // [2][8][PPITCH]

    const int tid = threadIdx.x;
    const int lt  = tid & 255;
    const bool gA = tid < 256;
    const int j   = lt >> 2;
    const int rg  = lt & 3;
    const int r0  = rg * 2;
    const int row_base = blockIdx.x * ROWS;

    for (int idx = tid; idx < 3 * 16384; idx += FTHR) {
        int w  = idx >> 14;
        int e  = idx & 16383;
        int kp = e & 3;
        int g  = (e >> 2) & 255;
        int kk = e >> 10;
        const float* src = (w == 0) ? w_hh0 : (w == 1) ? w_ih1 : w_hh1;
        sm[idx] = src[g * 64 + kk * 4 + kp];
    }
    for (int ii = tid; ii < 2 * 512; ii += FTHR) {
        int half = ii >> 9, rem = ii & 511;
        int r = rem & 7, u = rem >> 3;
        if (half == 0) h1b[2 * HBUF + r * IPITCH + u] = 0.0f;
        else           h2b[1 * HBUF + r * IPITCH + u] = 0.0f;
    }

    float bias1[4];
    #pragma unroll
    for (int q = 0; q < 4; q++) bias1[q] = b_ih1[q * 64 + j] + b_hh1[q * 64 + j];

    const float* prep = g_pre + (size_t)blockIdx.x * TT * 2048;
    float2 pcur[4];
    if (gA) {
        #pragma unroll
        for (int q = 0; q < 4; q++)
            pcur[q] = *reinterpret_cast<const float2*>(prep + (q * 64 + j) * 8 + r0);
    }

    float ca = 0.0f, cb = 0.0f;       // cell states (A: layer 0, B: layer 1)
    const float* wp0  = wq0  + j * 4;
    const float* wp1i = wq1i + j * 4;
    const float* wp1h = wq1h + j * 4;

    __syncthreads();

    for (int it = 0; it <= TT + 1; it++) {
        if (gA) {
            if (it <= TT) {
                const int t = it;
                float2 pnext[4];
                if (t < TT) {
                    int tn = (t + 1 < TT) ? (t + 1) : (TT - 1);
                    const float* pnb = prep + (size_t)tn * 2048;
                    #pragma unroll
                    for (int q = 0; q < 4; q++)
                        pnext[q] = *reinterpret_cast<const float2*>(pnb + (q * 64 + j) * 8 + r0);
                }

                unsigned long long acc0[2][4], accP[2][4];
                #pragma unroll
                for (int r = 0; r < 2; r++)
                    #pragma unroll
                    for (int q = 0; q < 4; q++) { acc0[r][q] = 0ull; accP[r][q] = 0ull; }

                const float* v0p = h1b + ((t + 2) % 3) * HBUF + r0 * IPITCH;
                const float* v1p = v0p + IPITCH;
                #pragma unroll
                for (int kk = 0; kk < 16; kk++) {
                    ulonglong2 v0 = *reinterpret_cast<const ulonglong2*>(v0p + kk * 4);
                    ulonglong2 v1 = *reinterpret_cast<const ulonglong2*>(v1p + kk * 4);
                    const float* wc = wp0 + kk * 1024;
                    #pragma unroll
                    for (int q = 0; q < 4; q++) {
                        ulonglong2 w2 = *reinterpret_cast<const ulonglong2*>(wc + q * 256);
                        fma2(acc0[0][q], v0.x, w2.x);
                        fma2(acc0[0][q], v0.y, w2.y);
                        fma2(acc0[1][q], v1.x, w2.x);
                        fma2(acc0[1][q], v1.y, w2.y);
                    }
                    if (kk < 8) {
                        const float* wci = wp1i + kk * 1024;
                        #pragma unroll
                        for (int q = 0; q < 4; q++) {
                            ulonglong2 wi = *reinterpret_cast<const ulonglong2*>(wci + q * 256);
                            fma2(accP[0][q], v0.x, wi.x);
                            fma2(accP[0][q], v0.y, wi.y);
                            fma2(accP[1][q], v1.x, wi.x);
                            fma2(accP[1][q], v1.y, wi.y);
                        }
                    }
                }

                if (t < TT) {
                    float z[2][4];
                    #pragma unroll
                    for (int q = 0; q < 4; q++) {
                        z[0][q] = sum2(acc0[0][q]) + pcur[q].x;
                        z[1][q] = sum2(acc0[1][q]) + pcur[q].y;
                    }
                    float i0, f0, o0, i1, f1, o1, g0, g1;
                    sig2(z[0][0], z[0][1], i0, f0);
                    sig2(z[0][3], z[1][0], o0, i1);
                    sig2(z[1][1], z[1][3], f1, o1);
                    tanh2(z[0][2], z[1][2], g0, g1);
                    ca = f0 * ca + i0 * g0;
                    cb = f1 * cb + i1 * g1;
                    float tc0, tc1;
                    tanh2(ca, cb, tc0, tc1);
                    float h0 = o0 * tc0;
                    float h1 = o1 * tc1;
                    float* nb = h1b + (t % 3) * HBUF;
                    nb[r0 * IPITCH + j]       = h0;
                    nb[(r0 + 1) * IPITCH + j] = h1;
                    #pragma unroll
                    for (int q = 0; q < 4; q++) pcur[q] = pnext[q];
                }
                if (t >= 1) {
                    float* pb = pAb + ((t - 1) & 1) * PBUF;
                    #pragma unroll
                    for (int q = 0; q < 4; q++) {
                        pb[r0 * PPITCH + q * 64 + j]       = sum2(accP[0][q]);
                        pb[(r0 + 1) * PPITCH + q * 64 + j] = sum2(accP[1][q]);
                    }
                }
            }
        } else {
            if (it >= 2) {
                const int s = it - 2;   // computing h2(s)
                // hoist partA(s) loads: ready since last barrier, latency
                // hidden under the k-loop below
                const float* pb = pAb + (s & 1) * PBUF;
                float pa[2][4];
                #pragma unroll
                for (int q = 0; q < 4; q++) {
                    pa[0][q] = pb[r0 * PPITCH + q * 64 + j];
                    pa[1][q] = pb[(r0 + 1) * PPITCH + q * 64 + j];
                }

                unsigned long long acc[2][4];
                #pragma unroll
                for (int r = 0; r < 2; r++)
                    #pragma unroll
                    for (int q = 0; q < 4; q++) acc[r][q] = 0ull;

                const float* u0p = h2b + ((s + 1) & 1) * HBUF + r0 * IPITCH;
                const float* u1p = u0p + IPITCH;
                const float* v0p = h1b + (s % 3) * HBUF + r0 * IPITCH;
                const float* v1p = v0p + IPITCH;
                #pragma unroll
                for (int kk = 0; kk < 16; kk++) {
                    ulonglong2 u0 = *reinterpret_cast<const ulonglong2*>(u0p + kk * 4);
                    ulonglong2 u1 = *reinterpret_cast<const ulonglong2*>(u1p + kk * 4);
                    const float* wcH = wp1h + kk * 1024;
                    #pragma unroll
                    for (int q = 0; q < 4; q++) {
                        ulonglong2 wH = *reinterpret_cast<const ulonglong2*>(wcH + q * 256);
                        fma2(acc[0][q], u0.x, wH.x);
                        fma2(acc[0][q], u0.y, wH.y);
                        fma2(acc[1][q], u1.x, wH.x);
                        fma2(acc[1][q], u1.y, wH.y);
                    }
                    if (kk >= 8) {
                        ulonglong2 v0 = *reinterpret_cast<const ulonglong2*>(v0p + kk * 4);
                        ulonglong2 v1 = *reinterpret_cast<const ulonglong2*>(v1p + kk * 4);
                        const float* wcI = wp1i + kk * 1024;
                        #pragma unroll
                        for (int q = 0; q < 4; q++) {
                            ulonglong2 wI = *reinterpret_cast<const ulonglong2*>(wcI + q * 256);
                            fma2(acc[0][q], v0.x, wI.x);
                            fma2(acc[0][q], v0.y, wI.y);
                            fma2(acc[1][q], v1.x, wI.x);
                            fma2(acc[1][q], v1.y, wI.y);
                        }
                    }
                }

                float z[2][4];
                #pragma unroll
                for (int q = 0; q < 4; q++) {
                    z[0][q] = sum2(acc[0][q]) + pa[0][q] + bias1[q];
                    z[1][q] = sum2(acc[1][q]) + pa[1][q] + bias1[q];
                }
                float i0, f0, o0, i1, f1, o1, g0, g1;
                sig2(z[0][0], z[0][1], i0, f0);
                sig2(z[0][3], z[1][0], o0, i1);
                sig2(z[1][1], z[1][3], f1, o1);
                tanh2(z[0][2], z[1][2], g0, g1);
                ca = f0 * ca + i0 * g0;
                cb = f1 * cb + i1 * g1;
                float tc0, tc1;
                tanh2(ca, cb, tc0, tc1);
                float h0 = o0 * tc0;
                float h1 = o1 * tc1;
                float* nb = h2b + (s & 1) * HBUF;
                nb[r0 * IPITCH + j]       = h0;
                nb[(r0 + 1) * IPITCH + j] = h1;
                if (s == TT - 1) {
                    g_hlast[(row_base + r0) * HH + j]     = h0;
                    g_hlast[(row_base + r0 + 1) * HH + j] = h1;
                }
            }
        }

        __syncthreads();
    }
}

// out[b][o] = softplus(h_last[b] . fc_w[o] + fc_b[o]),  O=32
__global__ void fc_softplus(const float* __restrict__ fc_w,
                            const float* __restrict__ fc_b,
                            float* __restrict__ out)
{
    __shared__ float wsh[64 * 32];
    __shared__ float bsh[32];
    const int tid = threadIdx.x;     // 128 threads

    for (int idx = tid; idx < 64 * 32; idx += 128) {
        int k = idx >> 5, o = idx & 31;
        wsh[idx] = fc_w[o * 64 + k];
    }
    if (tid < 32) bsh[tid] = fc_b[tid];
    __syncthreads();

    int gid = blockIdx.x * 128 + tid;
    int b = gid >> 5, o = gid & 31;
    const float* hr = g_hlast + b * 64;

    float z = bsh[o];
    #pragma unroll
    for (int k = 0; k < 64; k++)
        z += hr[k] * wsh[k * 32 + o];

    float r = (z > 20.0f) ? z : log1pf(__expf(z));
    out[gid] = r;
}

extern "C" void kernel_launch(void* const* d_in, const int* in_sizes, int n_in,
                              void* d_out, int out_size)
{
    (void)in_sizes; (void)n_in; (void)out_size;
    const float* x    = (const float*)d_in[0];
    const float* wih0 = (const float*)d_in[1];
    const float* whh0 = (const float*)d_in[2];
    const float* bih0 = (const float*)d_in[3];
    const float* bhh0 = (const float*)d_in[4];
    const float* wih1 = (const float*)d_in[5];
    const float* whh1 = (const float*)d_in[6];
    const float* bih1 = (const float*)d_in[7];
    const float* bhh1 = (const float*)d_in[8];
    const float* fcw  = (const float*)d_in[9];
    const float* fcb  = (const float*)d_in[10];
    float* out = (float*)d_out;

    const size_t smemA = (size_t)(16384 + 4 * ROWS * IPITCH) * sizeof(float);  // ~74.2 KB
    const size_t smemF = (size_t)(3 * 16384 + 3 * HBUF + 2 * HBUF + 2 * PBUF)
                         * sizeof(float);                                      // 224,128 B
    cudaFuncSetAttribute(gemm_pre,   cudaFuncAttributeMaxDynamicSharedMemorySize, (int)smemA);
    cudaFuncSetAttribute(lstm_fused, cudaFuncAttributeMaxDynamicSharedMemorySize, (int)smemF);

    dim3 pre_grid(BB / ROWS, TCH);

    gemm_pre<<<pre_grid, NTHR, smemA>>>(x, wih0, bih0, bhh0);
    lstm_fused<<<BB / ROWS, FTHR, smemF>>>(whh0, wih1, whh1, bih1, bhh1);
    fc_softplus<<<(BB * 32) / 128, 128>>>(fcw, fcb, out);
}